// round 2
// baseline (speedup 1.0000x reference)
#include <cuda_runtime.h>

// DrQ-v2 random-shift augmentation.
// x: [B=32, L=16, c=9, h=84, w=84] fp32  -> treated as 4608 planes of 84x84
// shift: [512, 2] int32 (sx, sy) in [0, 8]
// out[n,c,i,j] = x[n,c, clamp(i + sy - 4, 0, 83), clamp(j + sx - 4, 0, 83)]

#define PADV 4
#define NC 9
#define HH 84
#define WW 84
#define WV (WW / 4)          // 21 float4 per row
#define NVEC (HH * WV)       // 1764 float4 per plane
#define NPLANES (512 * NC)   // 4608

__global__ __launch_bounds__(256) void drq_shift_kernel(
    const float* __restrict__ x,
    const int* __restrict__ shift,
    float* __restrict__ out)
{
    const int p = blockIdx.x;          // plane index = n * 9 + c
    const int n = p / NC;              // image index
    const int dx = __ldg(&shift[2 * n]) - PADV;      // [-4, 4]
    const int dy = __ldg(&shift[2 * n + 1]) - PADV;  // [-4, 4]

    const float* __restrict__ xin = x + (size_t)p * (HH * WW);
    float* __restrict__ o = out + (size_t)p * (HH * WW);

    for (int t = threadIdx.x; t < NVEC; t += 256) {
        const int i  = t / WV;
        const int jv = t - i * WV;
        const int j0 = jv * 4;

        int si = i + dy;
        si = si < 0 ? 0 : (si > HH - 1 ? HH - 1 : si);
        const float* __restrict__ row = xin + si * WW;

        int c0 = j0 + dx;
        int c1 = c0 + 1;
        int c2 = c0 + 2;
        int c3 = c0 + 3;
        c0 = c0 < 0 ? 0 : (c0 > WW - 1 ? WW - 1 : c0);
        c1 = c1 < 0 ? 0 : (c1 > WW - 1 ? WW - 1 : c1);
        c2 = c2 < 0 ? 0 : (c2 > WW - 1 ? WW - 1 : c2);
        c3 = c3 < 0 ? 0 : (c3 > WW - 1 ? WW - 1 : c3);

        float4 v;
        v.x = __ldg(&row[c0]);
        v.y = __ldg(&row[c1]);
        v.z = __ldg(&row[c2]);
        v.w = __ldg(&row[c3]);

        reinterpret_cast<float4*>(o)[t] = v;
    }
}

extern "C" void kernel_launch(void* const* d_in, const int* in_sizes, int n_in,
                              void* d_out, int out_size)
{
    const float* x     = (const float*)d_in[0];
    const int*   shift = (const int*)d_in[1];
    float*       out   = (float*)d_out;

    drq_shift_kernel<<<NPLANES, 256>>>(x, shift, out);
}

// round 3
// speedup vs baseline: 1.0471x; 1.0471x over previous
#include <cuda_runtime.h>

// DrQ-v2 random-shift augmentation.
// x: [B=32, L=16, c=9, h=84, w=84] fp32  -> 4608 planes of 84x84
// shift: [512, 2] int32 (sx, sy) in [0, 8]
// out[n,c,i,j] = x[n,c, clamp(i + sy - 4, 0, 83), clamp(j + sx - 4, 0, 83)]

#define PADV 4
#define NC 9
#define HH 84
#define WW 84
#define WV (WW / 4)          // 21 float4 per row
#define NVEC (HH * WV)       // 1764 float4 per plane
#define NPLANES (512 * NC)   // 4608
#define TPB 256
#define KUNROLL 7            // 7 * 256 = 1792 >= 1764

__global__ __launch_bounds__(TPB) void drq_shift_kernel(
    const float* __restrict__ x,
    const int* __restrict__ shift,
    float* __restrict__ out)
{
    const int p = blockIdx.x;          // plane index = n * 9 + c
    const int n = p / NC;              // image index
    const int dx = __ldg(&shift[2 * n]) - PADV;      // [-4, 4]
    const int dy = __ldg(&shift[2 * n + 1]) - PADV;  // [-4, 4]

    const float* __restrict__ xin = x + (size_t)p * (HH * WW);
    float* __restrict__ o = out + (size_t)p * (HH * WW);

    const int t = threadIdx.x;

    float4 v[KUNROLL];

    // ---- Phase 1: issue all loads (unconditional; tail lanes load a safe
    // clamped address so ptxas can front-batch 28 independent LDGs) ----
    #pragma unroll
    for (int k = 0; k < KUNROLL; k++) {
        int vec = t + k * TPB;
        if (vec >= NVEC) vec = NVEC - 1;   // safe dummy for tail lanes

        const int i  = vec / WV;
        const int jv = vec - i * WV;
        const int j0 = jv * 4;

        int si = i + dy;
        si = si < 0 ? 0 : (si > HH - 1 ? HH - 1 : si);
        const float* __restrict__ row = xin + si * WW;

        int c0 = j0 + dx;
        int c1 = c0 + 1;
        int c2 = c0 + 2;
        int c3 = c0 + 3;
        c0 = c0 < 0 ? 0 : (c0 > WW - 1 ? WW - 1 : c0);
        c1 = c1 < 0 ? 0 : (c1 > WW - 1 ? WW - 1 : c1);
        c2 = c2 < 0 ? 0 : (c2 > WW - 1 ? WW - 1 : c2);
        c3 = c3 < 0 ? 0 : (c3 > WW - 1 ? WW - 1 : c3);

        v[k].x = __ldcs(&row[c0]);
        v[k].y = __ldcs(&row[c1]);
        v[k].z = __ldcs(&row[c2]);
        v[k].w = __ldcs(&row[c3]);
    }

    // ---- Phase 2: stores (streaming, evict-first) ----
    #pragma unroll
    for (int k = 0; k < KUNROLL; k++) {
        const int vec = t + k * TPB;
        if (vec < NVEC) {
            __stcs(reinterpret_cast<float4*>(o) + vec, v[k]);
        }
    }
}

extern "C" void kernel_launch(void* const* d_in, const int* in_sizes, int n_in,
                              void* d_out, int out_size)
{
    const float* x     = (const float*)d_in[0];
    const int*   shift = (const int*)d_in[1];
    float*       out   = (float*)d_out;

    drq_shift_kernel<<<NPLANES, TPB>>>(x, shift, out);
}